// round 16
// baseline (speedup 1.0000x reference)
#include <cuda_runtime.h>
#include <cuda_bf16.h>
#include <stdint.h>
#include <math.h>

#define BATCH 256
#define SEQ   256
#define IDIM  128
#define HID   1024
#define OUTC  10

#define NCTA  512
#define NTH   128
#define NSETS 8
#define SETROWS 32

// -------- device globals --------
__device__ uint32_t g_xs[(long)BATCH * SEQ * 8 * 16];    // packed x slots
__device__ uint32_t g_bs[8L * 8 * 9 * 128 * 16];         // packed W slabs (4.7MB)
__device__ uint32_t g_hs[2][BATCH * 64 * 16];            // packed h, parity-buffered
__device__ float    g_h[BATCH * HID];                    // plain h (final step)
__device__ float4   g_part[2][(long)NCTA * 4 * 8 * 32];  // partials, parity-buffered
__device__ unsigned int g_pdone[NSETS][8 * 32];          // per-(set,tile) partial ctrs
__device__ unsigned int g_hcol[NSETS][8][4 * 32];        // per-(set,tile,colgrp) h ctrs

// -------- helpers --------
static __device__ __forceinline__ uint32_t pk2(float a, float b) {
    __nv_bfloat162 t = __floats2bfloat162_rn(a, b);
    return *reinterpret_cast<uint32_t*>(&t);
}
static __device__ __forceinline__ float bf16rt(float v) {
    return __bfloat162float(__float2bfloat16_rn(v));
}
static __device__ __forceinline__ void mma16(float* c,
        uint32_t a0, uint32_t a1, uint32_t a2, uint32_t a3,
        uint32_t b0, uint32_t b1) {
    asm volatile(
        "mma.sync.aligned.m16n8k16.row.col.f32.bf16.bf16.f32 "
        "{%0,%1,%2,%3},{%4,%5,%6,%7},{%8,%9},{%0,%1,%2,%3};"
        : "+f"(c[0]), "+f"(c[1]), "+f"(c[2]), "+f"(c[3])
        : "r"(a0), "r"(a1), "r"(a2), "r"(a3), "r"(b0), "r"(b1));
}
static __device__ __forceinline__ float my_tanh(float v) {
    float e = __expf(2.0f * v);
    return 1.0f - 2.0f / (e + 1.0f);
}
static __device__ __forceinline__ void sig_release(unsigned int* p) {
    asm volatile("red.release.gpu.global.add.u32 [%0], 1;" :: "l"(p) : "memory");
}
static __device__ __forceinline__ unsigned ld_acq(const unsigned int* p) {
    unsigned v;
    asm volatile("ld.acquire.gpu.global.u32 %0, [%1];" : "=r"(v) : "l"(p) : "memory");
    return v;
}
static __device__ __forceinline__ void pack16(const float* v, uint4* dst) {
    #pragma unroll
    for (int t = 0; t < 4; t++) {
        const float a0 = v[2*t],   a1 = v[2*t+1];
        const float a8 = v[2*t+8], a9 = v[2*t+9];
        uint4 s;
        s.x = pk2(a0, a1);
        s.y = pk2(a8, a9);
        s.z = pk2(a0 - bf16rt(a0), a1 - bf16rt(a1));
        s.w = pk2(a8 - bf16rt(a8), a9 - bf16rt(a9));
        dst[t] = s;
    }
}

// -------- prep --------
__global__ void prep_kernel(const float* __restrict__ x,
                            const float* __restrict__ Whx,
                            const float* __restrict__ Whh) {
    const long tid = (long)blockIdx.x * blockDim.x + threadIdx.x;
    const long nt  = (long)gridDim.x * blockDim.x;
    for (long i = tid; i < (long)BATCH * SEQ * 8; i += nt) {
        const long bt = i >> 3;
        const int  g  = (int)(i & 7);
        const float* src = x + bt * IDIM + g * 16;
        float v[16];
        #pragma unroll
        for (int j = 0; j < 16; j++) v[j] = src[j];
        pack16(v, (uint4*)(g_xs + i * 16));
    }
    for (long i = tid; i < 8L * 8 * 9 * 128; i += nt) {
        const int col = (int)(i & 127);
        long tmp = i >> 7;
        const int c  = (int)(tmp % 9); tmp /= 9;
        const int ks = (int)(tmp & 7);
        const int tn = (int)(tmp >> 3);
        const int n  = tn * 128 + col;
        const int kbase = (c == 0) ? (HID + ks * 16) : (ks * 128 + (c - 1) * 16);
        float v[16];
        #pragma unroll
        for (int j = 0; j < 16; j++) {
            const int k = kbase + j;
            v[j] = (k < HID) ? Whh[(long)k * HID + n] : Whx[(long)(k - HID) * HID + n];
        }
        pack16(v, (uint4*)(g_bs + i * 16));
    }
    for (long i = tid; i < (long)BATCH * 64 * 16; i += nt) g_hs[0][i] = 0u;
    for (long i = tid; i < (long)BATCH * HID; i += nt)     g_h[i]  = 0.f;
    if (tid < NSETS * 8 * 32)
        g_pdone[tid / (8 * 32)][tid % (8 * 32)] = 0u;
    if (tid < NSETS * 8 * 4 * 32) {
        const int s = (int)(tid / (8 * 4 * 32));
        const int r = (int)(tid % (8 * 4 * 32));
        g_hcol[s][r / (4 * 32)][r % (4 * 32)] = 0u;
    }
}

// -------- main persistent kernel: 512 CTAs x 128 thr, 4 CTAs/SM --------
__global__ void __launch_bounds__(NTH, 4)
rnn_kernel(const float* __restrict__ bh,
           const float* __restrict__ Why,
           const float* __restrict__ bo,
           float* __restrict__ out) {
    __shared__ uint32_t sA[2 * 2 * 512];   // [buf][sub][32 rows *16 words] = 8KB
    __shared__ float red[4][OUTC];

    const int tid  = threadIdx.x;
    const int bid  = blockIdx.x;
    const int wid  = tid >> 5;
    const int lane = tid & 31;

    const int set   = bid >> 6;
    const int sbid  = bid & 63;
    const int tileN = sbid >> 3;
    const int ks    = sbid & 7;
    const int m0    = set * SETROWS;
    const int n0    = tileN * 128;

    const int grp = lane >> 2;
    const int tig = lane & 3;

    const int arow = tid >> 2;
    const int aq   = tid & 3;

    unsigned int* my_pctr = &g_pdone[set][tileN * 32];
    unsigned int* my_hcol = &g_hcol[set][tileN][(ks & 3) * 32];   // I signal this
    const unsigned int* dep_hcol = &g_hcol[set][ks][0];           // I consume these

    const uint4* bslab = (const uint4*)g_bs + (long)(tileN * 8 + ks) * (9 * 512);
    const int bfrag = (wid * 32 + grp) * 4 + tig;

    // reduce constants: 1 fragment per warp, f = ks*4 + wid
    const int f   = ks * 4 + wid;
    const int fmt = f >> 4;
    const int fw  = (f >> 2) & 3;
    const int fnt = f & 3;
    const int fq  = fmt * 4 + fnt;
    const int r_m = m0 + fmt * 16 + (lane >> 2);
    const int r_n = n0 + fw * 32 + fnt * 8 + (lane & 3) * 2;
    const long r_pbase = (((long)(set * 64 + tileN * 8) * 4 + fw) * 8 + fq) * 32 + lane;
    const float r_b0 = bh[r_n];
    const float r_b1 = bh[r_n + 1];
    const int jj = r_n & 15;
    const int r_hoff = (r_m * 64 + (r_n >> 4)) * 16 +
                       ((jj < 8) ? (jj >> 1) * 4 : ((jj - 8) >> 1) * 4 + 1);

    float acc[2][4][4];
    uint4 u0, u1;
    uint4 bvP[4], bvQ[4];
    const uint32_t* hbase_cur;

    auto ldgB = [&](int gk, uint4* bv) {
        const uint4* src = bslab + gk * 512 + bfrag;
        #pragma unroll
        for (int nt = 0; nt < 4; nt++) bv[nt] = src[nt * 32];
    };
    auto compute16 = [&](const uint4* bv, const uint32_t* ab) {
        const uint32_t* ap = ab + grp * 16 + tig * 4;
        uint4 ra[2][2];
        #pragma unroll
        for (int mt = 0; mt < 2; mt++) {
            ra[mt][0] = *(const uint4*)(ap + mt * 256);
            ra[mt][1] = *(const uint4*)(ap + mt * 256 + 128);
        }
        #pragma unroll
        for (int nt = 0; nt < 4; nt++) {
            #pragma unroll
            for (int mt = 0; mt < 2; mt++) {
                mma16(acc[mt][nt], ra[mt][0].x, ra[mt][1].x, ra[mt][0].y, ra[mt][1].y,
                      bv[nt].x, bv[nt].y);
                mma16(acc[mt][nt], ra[mt][0].x, ra[mt][1].x, ra[mt][0].y, ra[mt][1].y,
                      bv[nt].z, bv[nt].w);
                mma16(acc[mt][nt], ra[mt][0].z, ra[mt][1].z, ra[mt][0].w, ra[mt][1].w,
                      bv[nt].x, bv[nt].y);
            }
        }
    };
    // per-chunk h-ready wait: chunk i needs producers j=i and j=i+4 of tile `ks`
    // (counter (i)*32 gets 2 increments per step). Converged-warp acquire poll;
    // each thread's acquire orders its own subsequent h loads - no barrier needed.
    auto wait_col = [&](int i, unsigned tgt) {
        const unsigned int* p = dep_hcol + i * 32;
        while (ld_acq(p) < tgt) { }
    };
    auto ldg_h = [&](int i) {
        const uint4* src = (const uint4*)hbase_cur +
            ((long)(m0 + arow) * 64 + ks * 8 + 2 * i) * 4 + aq;
        u0 = src[0];
        u1 = src[4];
    };
    auto sts_h = [&](int buf) {
        uint4* d = (uint4*)sA + buf * 256 + arow * 4 + aq;
        d[0]   = u0;
        d[128] = u1;
    };
    auto zero_acc = [&]() {
        #pragma unroll
        for (int mt = 0; mt < 2; mt++)
            #pragma unroll
            for (int nt = 0; nt < 4; nt++)
                #pragma unroll
                for (int c = 0; c < 4; c++)
                    acc[mt][nt][c] = 0.f;
    };
    auto x_chunk = [&](int tt) {
        ldgB(0, bvP);
        const uint4* src = (const uint4*)g_xs +
            (((long)(m0 + arow) * SEQ + tt) * 8 + ks) * 4 + aq;
        uint4 xv = src[0];
        ((uint4*)sA)[arow * 4 + aq] = xv;     // buf0 sub0
        __syncthreads();
        compute16(bvP, sA);
        ldgB(1, bvP);
    };

    // ---- prologue: x chunk for t = 0 ----
    zero_acc();
    x_chunk(0);

    for (int t = 0; t < SEQ; t++) {
        const unsigned htgt = 2u * (unsigned)t;
        hbase_cur = g_hs[t & 1];

        // ---- 4 h chunks (k32), per-chunk column-ready waits ----
        wait_col(0, htgt);
        ldg_h(0);
        sts_h(1);
        __syncthreads();
        #pragma unroll 1
        for (int i = 0; i < 4; i++) {
            if (i < 3) {
                wait_col(i + 1, htgt);
                ldg_h(i + 1);
            }
            ldgB(2 + 2 * i, bvQ);
            const uint32_t* ab = sA + (((i + 1) & 1) * 1024);
            compute16(bvP, ab);
            if (i < 3) ldgB(3 + 2 * i, bvP);
            compute16(bvQ, ab + 512);
            if (i < 3) {
                sts_h(i & 1);
                __syncthreads();
            }
        }

        // ---- store partials (parity t) + release-signal ----
        {
            float4* pp = &g_part[t & 1][((long)(bid * 4 + wid) * 8) * 32 + lane];
            #pragma unroll
            for (int mt = 0; mt < 2; mt++)
                #pragma unroll
                for (int nt = 0; nt < 4; nt++) {
                    const int q = mt * 4 + nt;
                    pp[q * 32] = make_float4(acc[mt][nt][0], acc[mt][nt][1],
                                             acc[mt][nt][2], acc[mt][nt][3]);
                }
        }
        __syncthreads();
        if (tid == 0) sig_release(my_pctr);

        // ---- overlapped: x chunk of step t+1 (hides the pctr wait) ----
        zero_acc();
        if (t + 1 < SEQ) x_chunk(t + 1);

        // ---- wait: my tile's 8 partials stored ----
        if (tid == 0) {
            const unsigned target = 8u * (unsigned)(t + 1);
            while (ld_acq(my_pctr) < target) { }
        }
        __syncthreads();

        // ---- reduce: 1 fragment per warp ----
        {
            const float4* pbuf = g_part[t & 1];
            uint32_t* hdst = g_hs[(t + 1) & 1];
            float s0 = 0.f, s1 = 0.f, s2 = 0.f, s3 = 0.f;
            #pragma unroll
            for (int k2 = 0; k2 < 8; k2++) {
                float4 v = pbuf[r_pbase + (long)k2 * (4 * 8 * 32)];
                s0 += v.x; s1 += v.y; s2 += v.z; s3 += v.w;
            }
            const float t0 = my_tanh(s0 + r_b0);
            const float t1 = my_tanh(s1 + r_b1);
            const float t2 = my_tanh(s2 + r_b0);
            const float t3 = my_tanh(s3 + r_b1);
            const float f0 = bf16rt(t0), f1 = bf16rt(t1);
            const float f2 = bf16rt(t2), f3 = bf16rt(t3);
            hdst[r_hoff]            = pk2(t0, t1);
            hdst[r_hoff + 2]        = pk2(t0 - f0, t1 - f1);
            hdst[r_hoff + 8192]     = pk2(t2, t3);
            hdst[r_hoff + 8192 + 2] = pk2(t2 - f2, t3 - f3);
            if (t == SEQ - 1) {
                g_h[(long)r_m * HID + r_n]           = t0;
                g_h[(long)r_m * HID + r_n + 1]       = t1;
                g_h[(long)(r_m + 8) * HID + r_n]     = t2;
                g_h[(long)(r_m + 8) * HID + r_n + 1] = t3;
            }
        }
        __syncthreads();
        if (tid == 0) sig_release(my_hcol);
    }

    // ---- classifier + softmax: CTAs 0..255 handle one row each ----
    if (bid < BATCH) {
        const int row  = bid;
        const int setr = row >> 5;
        if (tid < 32) {
            const unsigned target = 2u * (unsigned)SEQ;
            const unsigned int* p = &g_hcol[setr][tid >> 2][(tid & 3) * 32];
            while (ld_acq(p) < target) { }
        }
        __syncthreads();

        float a[OUTC];
        #pragma unroll
        for (int o = 0; o < OUTC; o++) a[o] = 0.f;
        for (int k = tid; k < HID; k += NTH) {
            const float hv = g_h[(long)row * HID + k];
            const float* wr = Why + (long)k * OUTC;
            #pragma unroll
            for (int o = 0; o < OUTC; o++) a[o] += hv * wr[o];
        }
        #pragma unroll
        for (int o = 0; o < OUTC; o++)
            #pragma unroll
            for (int off = 16; off > 0; off >>= 1)
                a[o] += __shfl_down_sync(0xffffffffu, a[o], off);
        if (lane == 0) {
            #pragma unroll
            for (int o = 0; o < OUTC; o++) red[wid][o] = a[o];
        }
        __syncthreads();
        if (tid == 0) {
            float v[OUTC];
            float mx = -1e30f;
            #pragma unroll
            for (int o = 0; o < OUTC; o++) {
                v[o] = red[0][o] + red[1][o] + red[2][o] + red[3][o] + bo[o];
                mx = fmaxf(mx, v[o]);
            }
            float s = 0.f;
            #pragma unroll
            for (int o = 0; o < OUTC; o++) { v[o] = expf(v[o] - mx); s += v[o]; }
            const float inv = 1.0f / s;
            #pragma unroll
            for (int o = 0; o < OUTC; o++) out[row * OUTC + o] = v[o] * inv;
        }
    }
}

extern "C" void kernel_launch(void* const* d_in, const int* in_sizes, int n_in,
                              void* d_out, int out_size) {
    const float* x   = (const float*)d_in[0];
    const float* Whx = (const float*)d_in[1];
    const float* Whh = (const float*)d_in[2];
    const float* bh  = (const float*)d_in[3];
    const float* Why = (const float*)d_in[4];
    const float* bo  = (const float*)d_in[5];
    float* out = (float*)d_out;

    prep_kernel<<<1024, 256>>>(x, Whx, Whh);
    rnn_kernel<<<NCTA, NTH>>>(bh, Why, bo, out);
}

// round 17
// speedup vs baseline: 1.1417x; 1.1417x over previous
#include <cuda_runtime.h>
#include <cuda_bf16.h>
#include <stdint.h>
#include <math.h>

#define BATCH 256
#define SEQ   256
#define IDIM  128
#define HID   1024
#define OUTC  10

#define NCTA  512
#define NTH   128
#define NSETS 8
#define SETROWS 32

// -------- device globals --------
__device__ uint32_t g_xs[(long)BATCH * SEQ * 8 * 16];    // packed x slots
__device__ uint32_t g_bs[8L * 8 * 9 * 128 * 16];         // packed W slabs (4.7MB)
__device__ uint32_t g_hs[2][BATCH * 64 * 16];            // packed h, parity-buffered
__device__ float    g_h[BATCH * HID];                    // plain h (final step)
__device__ float4   g_part[2][(long)NCTA * 4 * 8 * 32];  // partials, parity-buffered
__device__ unsigned int g_pdone[NSETS][8 * 32];          // per-(set,tile) partial ctrs
__device__ unsigned int g_hdone[NSETS][8 * 32];          // per-(set,tile) h ctrs

// -------- helpers --------
static __device__ __forceinline__ uint32_t pk2(float a, float b) {
    __nv_bfloat162 t = __floats2bfloat162_rn(a, b);
    return *reinterpret_cast<uint32_t*>(&t);
}
static __device__ __forceinline__ float bf16rt(float v) {
    return __bfloat162float(__float2bfloat16_rn(v));
}
static __device__ __forceinline__ void mma16(float* c,
        uint32_t a0, uint32_t a1, uint32_t a2, uint32_t a3,
        uint32_t b0, uint32_t b1) {
    asm volatile(
        "mma.sync.aligned.m16n8k16.row.col.f32.bf16.bf16.f32 "
        "{%0,%1,%2,%3},{%4,%5,%6,%7},{%8,%9},{%0,%1,%2,%3};"
        : "+f"(c[0]), "+f"(c[1]), "+f"(c[2]), "+f"(c[3])
        : "r"(a0), "r"(a1), "r"(a2), "r"(a3), "r"(b0), "r"(b1));
}
static __device__ __forceinline__ float my_tanh(float v) {
    float e = __expf(2.0f * v);
    return 1.0f - 2.0f / (e + 1.0f);
}
static __device__ __forceinline__ void sig_release(unsigned int* p) {
    asm volatile("red.release.gpu.global.add.u32 [%0], 1;" :: "l"(p) : "memory");
}
static __device__ __forceinline__ unsigned ld_acq(const unsigned int* p) {
    unsigned v;
    asm volatile("ld.acquire.gpu.global.u32 %0, [%1];" : "=r"(v) : "l"(p) : "memory");
    return v;
}
static __device__ __forceinline__ void cp16(uint32_t saddr, const void* g) {
    asm volatile("cp.async.ca.shared.global [%0], [%1], 16;"
                 :: "r"(saddr), "l"(g) : "memory");
}
static __device__ __forceinline__ void cp_commit() {
    asm volatile("cp.async.commit_group;" ::: "memory");
}
static __device__ __forceinline__ void cp_wait0() {
    asm volatile("cp.async.wait_group 0;" ::: "memory");
}
static __device__ __forceinline__ void pack16(const float* v, uint4* dst) {
    #pragma unroll
    for (int t = 0; t < 4; t++) {
        const float a0 = v[2*t],   a1 = v[2*t+1];
        const float a8 = v[2*t+8], a9 = v[2*t+9];
        uint4 s;
        s.x = pk2(a0, a1);
        s.y = pk2(a8, a9);
        s.z = pk2(a0 - bf16rt(a0), a1 - bf16rt(a1));
        s.w = pk2(a8 - bf16rt(a8), a9 - bf16rt(a9));
        dst[t] = s;
    }
}

// -------- prep --------
__global__ void prep_kernel(const float* __restrict__ x,
                            const float* __restrict__ Whx,
                            const float* __restrict__ Whh) {
    const long tid = (long)blockIdx.x * blockDim.x + threadIdx.x;
    const long nt  = (long)gridDim.x * blockDim.x;
    for (long i = tid; i < (long)BATCH * SEQ * 8; i += nt) {
        const long bt = i >> 3;
        const int  g  = (int)(i & 7);
        const float* src = x + bt * IDIM + g * 16;
        float v[16];
        #pragma unroll
        for (int j = 0; j < 16; j++) v[j] = src[j];
        pack16(v, (uint4*)(g_xs + i * 16));
    }
    for (long i = tid; i < 8L * 8 * 9 * 128; i += nt) {
        const int col = (int)(i & 127);
        long tmp = i >> 7;
        const int c  = (int)(tmp % 9); tmp /= 9;
        const int ks = (int)(tmp & 7);
        const int tn = (int)(tmp >> 3);
        const int n  = tn * 128 + col;
        const int kbase = (c == 0) ? (HID + ks * 16) : (ks * 128 + (c - 1) * 16);
        float v[16];
        #pragma unroll
        for (int j = 0; j < 16; j++) {
            const int k = kbase + j;
            v[j] = (k < HID) ? Whh[(long)k * HID + n] : Whx[(long)(k - HID) * HID + n];
        }
        pack16(v, (uint4*)(g_bs + i * 16));
    }
    for (long i = tid; i < (long)BATCH * 64 * 16; i += nt) g_hs[0][i] = 0u;
    for (long i = tid; i < (long)BATCH * HID; i += nt)     g_h[i]  = 0.f;
    if (tid < NSETS * 8 * 32) {
        g_pdone[tid / (8 * 32)][tid % (8 * 32)] = 0u;
        g_hdone[tid / (8 * 32)][tid % (8 * 32)] = 0u;
    }
}

// -------- main persistent kernel: 512 CTAs x 128 thr, 4 CTAs/SM --------
__global__ void __launch_bounds__(NTH, 4)
rnn_kernel(const float* __restrict__ bh,
           const float* __restrict__ Why,
           const float* __restrict__ bo,
           float* __restrict__ out) {
    __shared__ __align__(16) uint32_t sA[2 * 2 * 512];   // [buf][sub][32 rows*16w] = 8KB
    __shared__ float red[4][OUTC];

    const int tid  = threadIdx.x;
    const int bid  = blockIdx.x;
    const int wid  = tid >> 5;     // warp = N position 0..3
    const int lane = tid & 31;

    const int set   = bid >> 6;          // 0..7 (32 batch rows each)
    const int sbid  = bid & 63;
    const int tileN = sbid >> 3;
    const int ks    = sbid & 7;
    const int m0    = set * SETROWS;
    const int n0    = tileN * 128;

    const int grp = lane >> 2;
    const int tig = lane & 3;

    const int arow = tid >> 2;     // staging row 0..31
    const int aq   = tid & 3;      // staging uint4 slot

    unsigned int* my_pctr = &g_pdone[set][tileN * 32];
    unsigned int* my_hctr = &g_hdone[set][tileN * 32];
    const unsigned int* dep_hctr = &g_hdone[set][ks * 32];

    // B gmem base (uint4 units): [(tileN*8+ks)][gk][row][4 uint4]
    const uint4* bslab = (const uint4*)g_bs + (long)(tileN * 8 + ks) * (9 * 512);
    const int bfrag = (wid * 32 + grp) * 4 + tig;

    // reduce constants: 1 fragment per warp, f = ks*4 + wid
    const int f   = ks * 4 + wid;
    const int fmt = f >> 4;
    const int fw  = (f >> 2) & 3;
    const int fnt = f & 3;
    const int fq  = fmt * 4 + fnt;
    const int r_m = m0 + fmt * 16 + (lane >> 2);
    const int r_n = n0 + fw * 32 + fnt * 8 + (lane & 3) * 2;
    const long r_pbase = (((long)(set * 64 + tileN * 8) * 4 + fw) * 8 + fq) * 32 + lane;
    const float r_b0 = bh[r_n];
    const float r_b1 = bh[r_n + 1];
    const int jj = r_n & 15;
    const int r_hoff = (r_m * 64 + (r_n >> 4)) * 16 +
                       ((jj < 8) ? (jj >> 1) * 4 : ((jj - 8) >> 1) * 4 + 1);

    const uint32_t sA_u32 = (uint32_t)__cvta_generic_to_shared(sA);
    const uint32_t stg_off = sA_u32 + (arow * 4 + aq) * 16;   // byte addr of my slot

    float acc[2][4][4];
    uint4 bvP[4], bvQ[4];
    const uint32_t* hbase_cur;

    auto ldgB = [&](int gk, uint4* bv) {
        const uint4* src = bslab + gk * 512 + bfrag;
        #pragma unroll
        for (int nt = 0; nt < 4; nt++) bv[nt] = src[nt * 32];
    };
    auto compute16 = [&](const uint4* bv, const uint32_t* ab) {
        const uint32_t* ap = ab + grp * 16 + tig * 4;
        uint4 ra[2][2];
        #pragma unroll
        for (int mt = 0; mt < 2; mt++) {
            ra[mt][0] = *(const uint4*)(ap + mt * 256);
            ra[mt][1] = *(const uint4*)(ap + mt * 256 + 128);
        }
        #pragma unroll
        for (int nt = 0; nt < 4; nt++) {
            #pragma unroll
            for (int mt = 0; mt < 2; mt++) {
                mma16(acc[mt][nt], ra[mt][0].x, ra[mt][1].x, ra[mt][0].y, ra[mt][1].y,
                      bv[nt].x, bv[nt].y);
                mma16(acc[mt][nt], ra[mt][0].x, ra[mt][1].x, ra[mt][0].y, ra[mt][1].y,
                      bv[nt].z, bv[nt].w);
                mma16(acc[mt][nt], ra[mt][0].z, ra[mt][1].z, ra[mt][0].w, ra[mt][1].w,
                      bv[nt].x, bv[nt].y);
            }
        }
    };
    // cp.async-stage h chunk i into buffer `buf` (2 x 16B per thread)
    auto cpa_h = [&](int i, int buf) {
        const char* src = (const char*)((const uint4*)hbase_cur +
            ((long)(m0 + arow) * 64 + ks * 8 + 2 * i) * 4 + aq);
        const uint32_t d = stg_off + buf * 4096;
        cp16(d, src);
        cp16(d + 2048, src + 64);
        cp_commit();
    };
    auto zero_acc = [&]() {
        #pragma unroll
        for (int mt = 0; mt < 2; mt++)
            #pragma unroll
            for (int nt = 0; nt < 4; nt++)
                #pragma unroll
                for (int c = 0; c < 4; c++)
                    acc[mt][nt][c] = 0.f;
    };
    auto x_chunk = [&](int tt) {
        ldgB(0, bvP);
        const char* src = (const char*)((const uint4*)g_xs +
            (((long)(m0 + arow) * SEQ + tt) * 8 + ks) * 4 + aq);
        cp16(stg_off, src);                    // buf0 sub0
        cp_commit();
        cp_wait0();
        __syncthreads();
        compute16(bvP, sA);
        ldgB(1, bvP);                          // pre-load first h group's B
    };

    // ---- prologue: x chunk for t = 0 ----
    zero_acc();
    x_chunk(0);

    for (int t = 0; t < SEQ; t++) {
        // ---- per-warp dep poll: producer tile `ks` finished reduce of step t-1 ----
        if (lane == 0) {
            const unsigned target = 8u * (unsigned)t;
            while (ld_acq(dep_hctr) < target) { }
        }
        __syncwarp();

        hbase_cur = g_hs[t & 1];

        // ---- 4 h chunks (k32), cp.async double-buffered, B register-pipelined ----
        cpa_h(0, 1);
        cp_wait0();
        __syncthreads();
        #pragma unroll 1
        for (int i = 0; i < 4; i++) {
            if (i < 3) cpa_h(i + 1, i & 1);
            ldgB(2 + 2 * i, bvQ);
            const uint32_t* ab = sA + (((i + 1) & 1) * 1024);
            compute16(bvP, ab);
            if (i < 3) ldgB(3 + 2 * i, bvP);
            compute16(bvQ, ab + 512);
            if (i < 3) {
                cp_wait0();
                __syncthreads();
            }
        }

        // ---- store partials (parity t) + release-signal ----
        {
            float4* pp = &g_part[t & 1][((long)(bid * 4 + wid) * 8) * 32 + lane];
            #pragma unroll
            for (int mt = 0; mt < 2; mt++)
                #pragma unroll
                for (int nt = 0; nt < 4; nt++) {
                    const int q = mt * 4 + nt;
                    pp[q * 32] = make_float4(acc[mt][nt][0], acc[mt][nt][1],
                                             acc[mt][nt][2], acc[mt][nt][3]);
                }
        }
        __syncthreads();
        if (tid == 0) sig_release(my_pctr);

        // ---- overlapped: x chunk of step t+1 (hides the pctr wait) ----
        zero_acc();
        if (t + 1 < SEQ) x_chunk(t + 1);   // safe: buf0's last reader barriered above

        // ---- wait: my tile's 8 partials stored ----
        if (tid == 0) {
            const unsigned target = 8u * (unsigned)(t + 1);
            while (ld_acq(my_pctr) < target) { }
        }
        __syncthreads();

        // ---- reduce: 1 fragment per warp ----
        {
            const float4* pbuf = g_part[t & 1];
            uint32_t* hdst = g_hs[(t + 1) & 1];
            float s0 = 0.f, s1 = 0.f, s2 = 0.f, s3 = 0.f;
            #pragma unroll
            for (int k2 = 0; k2 < 8; k2++) {
                float4 v = pbuf[r_pbase + (long)k2 * (4 * 8 * 32)];
                s0 += v.x; s1 += v.y; s2 += v.z; s3 += v.w;
            }
            const float t0 = my_tanh(s0 + r_b0);
            const float t1 = my_tanh(s1 + r_b1);
            const float t2 = my_tanh(s2 + r_b0);
            const float t3 = my_tanh(s3 + r_b1);
            const float f0 = bf16rt(t0), f1 = bf16rt(t1);
            const float f2 = bf16rt(t2), f3 = bf16rt(t3);
            hdst[r_hoff]            = pk2(t0, t1);
            hdst[r_hoff + 2]        = pk2(t0 - f0, t1 - f1);
            hdst[r_hoff + 8192]     = pk2(t2, t3);
            hdst[r_hoff + 8192 + 2] = pk2(t2 - f2, t3 - f3);
            if (t == SEQ - 1) {
                g_h[(long)r_m * HID + r_n]           = t0;
                g_h[(long)r_m * HID + r_n + 1]       = t1;
                g_h[(long)(r_m + 8) * HID + r_n]     = t2;
                g_h[(long)(r_m + 8) * HID + r_n + 1] = t3;
            }
        }
        __syncthreads();
        if (tid == 0) sig_release(my_hctr);
    }

    // ---- classifier + softmax: CTAs 0..255 handle one row each ----
    if (bid < BATCH) {
        const int row  = bid;
        const int setr = row >> 5;
        if (tid < 8) {
            const unsigned target = 8u * (unsigned)SEQ;
            while (ld_acq(&g_hdone[setr][tid * 32]) < target) { }
        }
        __syncthreads();

        float a[OUTC];
        #pragma unroll
        for (int o = 0; o < OUTC; o++) a[o] = 0.f;
        for (int k = tid; k < HID; k += NTH) {
            const float hv = g_h[(long)row * HID + k];
            const float* wr = Why + (long)k * OUTC;
            #pragma unroll
            for (int o = 0; o < OUTC; o++) a[o] += hv * wr[o];
        }
        #pragma unroll
        for (int o = 0; o < OUTC; o++)
            #pragma unroll
            for (int off = 16; off > 0; off >>= 1)
                a[o] += __shfl_down_sync(0xffffffffu, a[o], off);
        if (lane == 0) {
            #pragma unroll
            for (int o = 0; o < OUTC; o++) red[wid][o] = a[o];
        }
        __syncthreads();
        if (tid == 0) {
            float v[OUTC];
            float mx = -1e30f;
            #pragma unroll
            for (int o = 0; o < OUTC; o++) {
                v[o] = red[0][o] + red[1][o] + red[2][o] + red[3][o] + bo[o];
                mx = fmaxf(mx, v[o]);
            }
            float s = 0.f;
            #pragma unroll
            for (int o = 0; o < OUTC; o++) { v[o] = expf(v[o] - mx); s += v[o]; }
            const float inv = 1.0f / s;
            #pragma unroll
            for (int o = 0; o < OUTC; o++) out[row * OUTC + o] = v[o] * inv;
        }
    }
}

extern "C" void kernel_launch(void* const* d_in, const int* in_sizes, int n_in,
                              void* d_out, int out_size) {
    const float* x   = (const float*)d_in[0];
    const float* Whx = (const float*)d_in[1];
    const float* Whh = (const float*)d_in[2];
    const float* bh  = (const float*)d_in[3];
    const float* Why = (const float*)d_in[4];
    const float* bo  = (const float*)d_in[5];
    float* out = (float*)d_out;

    prep_kernel<<<1024, 256>>>(x, Whx, Whh);
    rnn_kernel<<<NCTA, NTH>>>(bh, Why, bo, out);
}